// round 7
// baseline (speedup 1.0000x reference)
#include <cuda_runtime.h>
#include <cuda_fp16.h>
#include <math.h>

#define NN 100000
#define NE 1600000
#define DH 128
#define DO 64
#define NB 98   // ceil(NN/1024)

// ---- scratch (static device globals; no allocation allowed) ----
__device__ __half g_h16  [(size_t)NN * DH]; // layer1 gemm output (fp16)
__device__ __half g_h2_16[(size_t)NN * DO]; // layer2 gemm output (fp16)
__device__ __half g_agg16[(size_t)NN * DH]; // layer1 activated output (fp16)
__device__ __half g_w1h[DH * DH], g_w1l[DH * DH];
__device__ __half g_w2h[DH * DO], g_w2l[DH * DO];
__device__ float  g_dinv [NN];
__device__ int    g_ecnt [NN];
__device__ int    g_rowptr[NN + 1];
__device__ int    g_bsum[NB];
__device__ int    g_boff[NB];
__device__ int2   g_epair[NE];
__device__ unsigned g_odd_or;               // 0 => edge_index is int64

// ---------------------------------------------------------------
__global__ void k_init(const unsigned* __restrict__ ei) {
    int i = blockIdx.x * blockDim.x + threadIdx.x;
    if (i < NN) g_ecnt[i] = 0;
    if (i < 65536) {
        unsigned v = ei[2 * i + 1];
        #pragma unroll
        for (int o = 16; o; o >>= 1) v |= __shfl_xor_sync(0xffffffffu, v, o);
        if ((threadIdx.x & 31) == 0 && v) atomicOr(&g_odd_or, v);
    }
}

__global__ void k_count(const unsigned* __restrict__ ei) {
    int e = blockIdx.x * blockDim.x + threadIdx.x;
    if (e >= NE) return;
    bool is64 = (g_odd_or == 0u);
    int d = (int)(is64 ? ei[2 * ((size_t)NE + e)] : ei[(size_t)NE + e]);
    atomicAdd(&g_ecnt[d], 1);
}

// W hi/lo fp16 splits (once).
__global__ void k_wsplit(const float* __restrict__ W1, const float* __restrict__ W2) {
    int i = blockIdx.x * blockDim.x + threadIdx.x;
    if (i < DH * DH) {
        float v = W1[i];
        __half h = __float2half_rn(v);
        g_w1h[i] = h;
        g_w1l[i] = __float2half_rn(v - __half2float(h));
    }
    if (i < DH * DO) {
        float v = W2[i];
        __half h = __float2half_rn(v);
        g_w2h[i] = h;
        g_w2l[i] = __float2half_rn(v - __half2float(h));
    }
}

__global__ __launch_bounds__(1024) void k_p1() {
    __shared__ int ws[32];
    int t = threadIdx.x, idx = blockIdx.x * 1024 + t;
    int v = (idx < NN) ? g_ecnt[idx] : 0;
    if (idx < NN) g_dinv[idx] = rsqrtf((float)(v + 1));
    int s = v;
    #pragma unroll
    for (int o = 16; o; o >>= 1) s += __shfl_xor_sync(0xffffffffu, s, o);
    if ((t & 31) == 0) ws[t >> 5] = s;
    __syncthreads();
    if (t < 32) {
        int x = ws[t];
        #pragma unroll
        for (int o = 16; o; o >>= 1) x += __shfl_xor_sync(0xffffffffu, x, o);
        if (t == 0) g_bsum[blockIdx.x] = x;
    }
}

__global__ void k_p2() {
    __shared__ int ws[4];
    int t = threadIdx.x, lane = t & 31, w = t >> 5;
    int v = (t < NB) ? g_bsum[t] : 0;
    int p = v;
    #pragma unroll
    for (int o = 1; o < 32; o <<= 1) {
        int u = __shfl_up_sync(0xffffffffu, p, o);
        if (lane >= o) p += u;
    }
    if (lane == 31) ws[w] = p;
    __syncthreads();
    int woff = 0;
    #pragma unroll
    for (int k = 0; k < 4; k++) if (k < w) woff += ws[k];
    int incl = p + woff;
    if (t < NB) g_boff[t] = incl - v;
    if (t == NB - 1) g_rowptr[NN] = incl;
}

__global__ __launch_bounds__(1024) void k_p3() {
    __shared__ int ws[32];
    int t = threadIdx.x, lane = t & 31, w = t >> 5;
    int idx = blockIdx.x * 1024 + t;
    int v = (idx < NN) ? g_ecnt[idx] : 0;
    int p = v;
    #pragma unroll
    for (int o = 1; o < 32; o <<= 1) {
        int u = __shfl_up_sync(0xffffffffu, p, o);
        if (lane >= o) p += u;
    }
    if (lane == 31) ws[w] = p;
    __syncthreads();
    if (t < 32) {
        int x = ws[t];
        #pragma unroll
        for (int o = 1; o < 32; o <<= 1) {
            int u = __shfl_up_sync(0xffffffffu, x, o);
            if (lane >= o) x += u;
        }
        ws[t] = x - ws[t];
    }
    __syncthreads();
    if (idx < NN) {
        g_rowptr[idx] = g_boff[blockIdx.x] + ws[w] + p - v;
        g_ecnt[idx] = 0;
    }
}

__global__ void k_fill(const unsigned* __restrict__ ei) {
    int e = blockIdx.x * blockDim.x + threadIdx.x;
    if (e >= NE) return;
    bool is64 = (g_odd_or == 0u);
    int s = (int)(is64 ? ei[2 * (size_t)e]        : ei[e]);
    int d = (int)(is64 ? ei[2 * ((size_t)NE + e)] : ei[(size_t)NE + e]);
    float nrm = g_dinv[s] * g_dinv[d];
    int pos = g_rowptr[d] + atomicAdd(&g_ecnt[d], 1);
    g_epair[pos] = make_int2(s, __float_as_int(nrm));
}

// ---------------------------------------------------------------
// Split-fp16 tensor-core GEMM (m16n8k16, fp32 accum).
// LAYER==0: X = x (fp32, split hi/lo), W = g_w1{h,l}; 3 mmas/tile.  H = g_h16.
// LAYER==1: X = g_agg16 (exact fp16),  W = g_w2{h,l}; 2 mmas/tile.  H = g_h2_16.
__device__ __forceinline__ void mma16(float* c, const unsigned* a, const unsigned* b) {
    asm volatile("mma.sync.aligned.m16n8k16.row.col.f32.f16.f16.f32 "
                 "{%0,%1,%2,%3}, {%4,%5,%6,%7}, {%8,%9}, {%0,%1,%2,%3};"
                 : "+f"(c[0]), "+f"(c[1]), "+f"(c[2]), "+f"(c[3])
                 : "r"(a[0]), "r"(a[1]), "r"(a[2]), "r"(a[3]), "r"(b[0]), "r"(b[1]));
}
__device__ __forceinline__ void ldsm_x4(unsigned* r, unsigned addr) {
    asm volatile("ldmatrix.sync.aligned.m8n8.x4.shared.b16 {%0,%1,%2,%3}, [%4];"
                 : "=r"(r[0]), "=r"(r[1]), "=r"(r[2]), "=r"(r[3]) : "r"(addr));
}
__device__ __forceinline__ void ldsm_x4t(unsigned* r, unsigned addr) {
    asm volatile("ldmatrix.sync.aligned.m8n8.x4.trans.shared.b16 {%0,%1,%2,%3}, [%4];"
                 : "=r"(r[0]), "=r"(r[1]), "=r"(r[2]), "=r"(r[3]) : "r"(addr));
}

template <int BN, int LAYER>
__global__ __launch_bounds__(256) void k_mma(const float* __restrict__ Xext) {
    constexpr int BM = 128, BK = 32;
    constexpr int XS = 40;            // X smem stride (halves): conflict-free ldmatrix
    constexpr int WS = BN + 8;        // W smem stride (halves): conflict-free ldmatrix
    constexpr int NT = BN / 16;       // 8x8 n-tiles per warp (8 or 4)

    __shared__ alignas(16) __half XsH[BM * XS];
    __shared__ alignas(16) __half XsL[LAYER == 0 ? BM * XS : 8];
    __shared__ alignas(16) __half WsH[BK * WS];
    __shared__ alignas(16) __half WsL[BK * WS];

    const __half* Wh = (LAYER == 0) ? g_w1h : g_w2h;
    const __half* Wl = (LAYER == 0) ? g_w1l : g_w2l;
    __half* H = (LAYER == 0) ? g_h16 : g_h2_16;

    int tid = threadIdx.x;
    int lane = tid & 31, wid = tid >> 5;
    int wm = (wid & 3) * 32;          // warp m offset (4 m-warps)
    int wn = (wid >> 2) * (BN / 2);   // warp n offset (2 n-warps)
    int row0 = blockIdx.x * BM;

    unsigned xh_base = (unsigned)__cvta_generic_to_shared(XsH);
    unsigned xl_base = (unsigned)__cvta_generic_to_shared(XsL);
    unsigned wh_base = (unsigned)__cvta_generic_to_shared(WsH);
    unsigned wl_base = (unsigned)__cvta_generic_to_shared(WsL);

    float acc[2][NT][4];
    #pragma unroll
    for (int mt = 0; mt < 2; mt++)
        #pragma unroll
        for (int nt = 0; nt < NT; nt++)
            #pragma unroll
            for (int q = 0; q < 4; q++) acc[mt][nt][q] = 0.f;

    // ldmatrix lane addressing (halves offsets)
    int a_row = lane & 15, a_col = (lane >> 4) * 8;                    // A x4
    int b_row = (lane & 7) + ((lane >> 3) & 1) * 8;                    // B x4.trans
    int b_col = (lane >> 4) * 8;

    for (int kc = 0; kc < 128; kc += BK) {
        // ---- X tile: BM x BK ----
        #pragma unroll
        for (int f = tid; f < BM * (BK / 4); f += 256) {
            int rr = f >> 3, kq = (f & 7) * 4;
            int grow = row0 + rr;
            if (LAYER == 0) {
                float4 v = make_float4(0.f, 0.f, 0.f, 0.f);
                if (grow < NN) v = *(const float4*)(Xext + (size_t)grow * 128 + kc + kq);
                __half h0 = __float2half_rn(v.x), h1 = __float2half_rn(v.y);
                __half h2 = __float2half_rn(v.z), h3 = __float2half_rn(v.w);
                __half l0 = __float2half_rn(v.x - __half2float(h0));
                __half l1 = __float2half_rn(v.y - __half2float(h1));
                __half l2 = __float2half_rn(v.z - __half2float(h2));
                __half l3 = __float2half_rn(v.w - __half2float(h3));
                __half2 H0 = __halves2half2(h0, h1), H1 = __halves2half2(h2, h3);
                __half2 L0 = __halves2half2(l0, l1), L1 = __halves2half2(l2, l3);
                *(uint2*)(XsH + rr * XS + kq) =
                    make_uint2(*(unsigned*)&H0, *(unsigned*)&H1);
                *(uint2*)(XsL + rr * XS + kq) =
                    make_uint2(*(unsigned*)&L0, *(unsigned*)&L1);
            } else {
                uint2 u = make_uint2(0u, 0u);
                if (grow < NN) u = *(const uint2*)(g_agg16 + (size_t)grow * 128 + kc + kq);
                *(uint2*)(XsH + rr * XS + kq) = u;
            }
        }
        // ---- W tile: BK x BN (hi+lo planes, uint4 = 8 halves) ----
        #pragma unroll
        for (int f = tid; f < BK * (BN / 8); f += 256) {
            int kk = f / (BN / 8), nq = (f % (BN / 8)) * 8;
            *(uint4*)(WsH + kk * WS + nq) = *(const uint4*)(Wh + (size_t)(kc + kk) * BN + nq);
            *(uint4*)(WsL + kk * WS + nq) = *(const uint4*)(Wl + (size_t)(kc + kk) * BN + nq);
        }
        __syncthreads();

        #pragma unroll
        for (int k16 = 0; k16 < BK; k16 += 16) {
            unsigned aH[2][4], aL[2][4];
            #pragma unroll
            for (int mt = 0; mt < 2; mt++) {
                unsigned off = (unsigned)(((wm + mt * 16 + a_row) * XS + k16 + a_col) * 2);
                ldsm_x4(aH[mt], xh_base + off);
                if (LAYER == 0) ldsm_x4(aL[mt], xl_base + off);
            }
            #pragma unroll
            for (int np = 0; np < NT / 2; np++) {     // pairs of n-tiles
                unsigned off = (unsigned)(((k16 + b_row) * WS + wn + np * 16 + b_col) * 2);
                unsigned bh[4], bl[4];
                ldsm_x4t(bh, wh_base + off);
                ldsm_x4t(bl, wl_base + off);
                #pragma unroll
                for (int h = 0; h < 2; h++) {         // the two n-tiles in the pair
                    int nt = np * 2 + h;
                    #pragma unroll
                    for (int mt = 0; mt < 2; mt++) {
                        if (LAYER == 0) mma16(acc[mt][nt], aL[mt], bh + 2 * h);
                        mma16(acc[mt][nt], aH[mt], bl + 2 * h);
                        mma16(acc[mt][nt], aH[mt], bh + 2 * h);
                    }
                }
            }
        }
        __syncthreads();
    }

    // epilogue: fp16 store
    int g = lane >> 2, r = lane & 3;
    #pragma unroll
    for (int mt = 0; mt < 2; mt++) {
        int rA = row0 + wm + mt * 16 + g;
        #pragma unroll
        for (int nt = 0; nt < NT; nt++) {
            int col = wn + nt * 8 + 2 * r;
            if (rA < NN)
                *(__half2*)(H + (size_t)rA * BN + col) =
                    __floats2half2_rn(acc[mt][nt][0], acc[mt][nt][1]);
            if (rA + 8 < NN)
                *(__half2*)(H + (size_t)(rA + 8) * BN + col) =
                    __floats2half2_rn(acc[mt][nt][2], acc[mt][nt][3]);
        }
    }
}

// ---------------------------------------------------------------
__device__ __forceinline__ float elu1(float x) { return x > 0.f ? x : expm1f(x); }

__device__ __forceinline__ void acc128(float* acc, uint2 u, float n) {
    float2 f0 = __half22float2(*reinterpret_cast<__half2*>(&u.x));
    float2 f1 = __half22float2(*reinterpret_cast<__half2*>(&u.y));
    acc[0] += f0.x * n; acc[1] += f0.y * n;
    acc[2] += f1.x * n; acc[3] += f1.y * n;
}
__device__ __forceinline__ void acc64(float* acc, unsigned u, float n) {
    float2 f0 = __half22float2(*reinterpret_cast<__half2*>(&u));
    acc[0] += f0.x * n; acc[1] += f0.y * n;
}

template <int D>
__global__ void k_agg(const float* __restrict__ bias, float* __restrict__ outp) {
    int node = (blockIdx.x * blockDim.x + threadIdx.x) >> 5;
    if (node >= NN) return;
    int lane = threadIdx.x & 31;
    constexpr int VL = D / 32;

    const __half* H = (D == DH) ? g_h16 : g_h2_16;

    float acc[VL];
    #pragma unroll
    for (int k = 0; k < VL; k++) acc[k] = 0.f;

    int beg = g_rowptr[node], end = g_rowptr[node + 1];
    int j = beg;
    for (; j + 8 <= end; j += 8) {
        int2 p[8];
        #pragma unroll
        for (int i = 0; i < 8; i++) p[i] = __ldg(&g_epair[j + i]);
        if (D == DH) {
            uint2 u[8];
            #pragma unroll
            for (int i = 0; i < 8; i++)
                u[i] = __ldg((const uint2*)(H + (size_t)p[i].x * D) + lane);
            #pragma unroll
            for (int i = 0; i < 8; i++)
                acc128(acc, u[i], __int_as_float(p[i].y));
        } else {
            unsigned u[8];
            #pragma unroll
            for (int i = 0; i < 8; i++)
                u[i] = __ldg((const unsigned*)(H + (size_t)p[i].x * D) + lane);
            #pragma unroll
            for (int i = 0; i < 8; i++)
                acc64(acc, u[i], __int_as_float(p[i].y));
        }
    }
    for (; j < end; j++) {
        int2 p = __ldg(&g_epair[j]);
        float n = __int_as_float(p.y);
        if (D == DH) {
            uint2 u = __ldg((const uint2*)(H + (size_t)p.x * D) + lane);
            acc128(acc, u, n);
        } else {
            unsigned u = __ldg((const unsigned*)(H + (size_t)p.x * D) + lane);
            acc64(acc, u, n);
        }
    }

    float di = g_dinv[node], d2 = di * di;
    if (D == DH) {
        uint2 us = __ldg((const uint2*)(H + (size_t)node * D) + lane);
        float hv[4] = {0.f, 0.f, 0.f, 0.f};
        acc128(hv, us, d2);
        float4 bv = *(const float4*)(bias + lane * 4);
        float r0 = elu1(acc[0] + hv[0] + bv.x);
        float r1 = elu1(acc[1] + hv[1] + bv.y);
        float r2 = elu1(acc[2] + hv[2] + bv.z);
        float r3 = elu1(acc[3] + hv[3] + bv.w);
        __half2 o0 = __floats2half2_rn(r0, r1);
        __half2 o1 = __floats2half2_rn(r2, r3);
        *((uint2*)(g_agg16 + (size_t)node * D) + lane) =
            make_uint2(*reinterpret_cast<unsigned*>(&o0), *reinterpret_cast<unsigned*>(&o1));
    } else {
        unsigned us = __ldg((const unsigned*)(H + (size_t)node * D) + lane);
        float hv[2] = {0.f, 0.f};
        acc64(hv, us, d2);
        float2 bv = *(const float2*)(bias + lane * 2);
        float2 rr;
        rr.x = elu1(acc[0] + hv[0] + bv.x);
        rr.y = elu1(acc[1] + hv[1] + bv.y);
        *(float2*)(outp + (size_t)node * D + lane * 2) = rr;
    }
}

// ---------------------------------------------------------------
extern "C" void kernel_launch(void* const* d_in, const int* in_sizes, int n_in,
                              void* d_out, int out_size) {
    const float*    x  = (const float*)d_in[0];
    const unsigned* ei = (const unsigned*)d_in[1];
    const float*    W1 = (const float*)d_in[2];
    const float*    b1 = (const float*)d_in[3];
    const float*    W2 = (const float*)d_in[4];
    const float*    b2 = (const float*)d_in[5];
    float*          out = (float*)d_out;

    k_init  <<<(NN + 255) / 256, 256>>>(ei);            // 0
    k_count <<<(NE + 255) / 256, 256>>>(ei);            // 1
    k_wsplit<<<64, 256>>>(W1, W2);                      // 2
    k_mma<DH, 0><<<(NN + 127) / 128, 256>>>(x);         // 3 (profiled slot)
    k_p1    <<<NB, 1024>>>();                           // 4
    k_p2    <<<1, 128>>>();                             // 5
    k_p3    <<<NB, 1024>>>();                           // 6
    k_fill  <<<(NE + 255) / 256, 256>>>(ei);            // 7

    k_agg<DH><<<(NN * 32 + 255) / 256, 256>>>(b1, nullptr);   // 8
    k_mma<DO, 1><<<(NN + 127) / 128, 256>>>(nullptr);         // 9
    k_agg<DO><<<(NN * 32 + 255) / 256, 256>>>(b2, out);       // 10

    (void)in_sizes; (void)n_in; (void)out_size;
}

// round 8
// speedup vs baseline: 1.0005x; 1.0005x over previous
#include <cuda_runtime.h>
#include <cuda_fp16.h>
#include <math.h>

#define NN 100000
#define NE 1600000
#define DH 128
#define DO 64
#define NB 98   // ceil(NN/1024)

// ---- scratch (static device globals; no allocation allowed) ----
__device__ __half g_h16  [(size_t)NN * DH]; // layer1 gemm output (fp16)
__device__ __half g_h2_16[(size_t)NN * DO]; // layer2 gemm output (fp16)
__device__ __half g_agg16[(size_t)NN * DH]; // layer1 activated output (fp16)
__device__ __half g_w1h[DH * DH], g_w1l[DH * DH];
__device__ __half g_w2h[DH * DO], g_w2l[DH * DO];
__device__ float  g_dinv [NN];
__device__ int    g_ecnt [NN];
__device__ int    g_rowptr[NN + 1];
__device__ int    g_bsum[NB];
__device__ int    g_boff[NB];
__device__ int2   g_epair[NE];
__device__ unsigned g_odd_or;               // 0 => edge_index is int64

// ---------------------------------------------------------------
__global__ void k_init(const unsigned* __restrict__ ei) {
    int i = blockIdx.x * blockDim.x + threadIdx.x;
    if (i < NN) g_ecnt[i] = 0;
    if (i < 65536) {
        unsigned v = ei[2 * i + 1];
        #pragma unroll
        for (int o = 16; o; o >>= 1) v |= __shfl_xor_sync(0xffffffffu, v, o);
        if ((threadIdx.x & 31) == 0 && v) atomicOr(&g_odd_or, v);
    }
}

__global__ void k_count(const unsigned* __restrict__ ei) {
    int e = blockIdx.x * blockDim.x + threadIdx.x;
    if (e >= NE) return;
    bool is64 = (g_odd_or == 0u);
    int d = (int)(is64 ? ei[2 * ((size_t)NE + e)] : ei[(size_t)NE + e]);
    atomicAdd(&g_ecnt[d], 1);
}

// W hi/lo fp16 splits (once).
__global__ void k_wsplit(const float* __restrict__ W1, const float* __restrict__ W2) {
    int i = blockIdx.x * blockDim.x + threadIdx.x;
    if (i < DH * DH) {
        float v = W1[i];
        __half h = __float2half_rn(v);
        g_w1h[i] = h;
        g_w1l[i] = __float2half_rn(v - __half2float(h));
    }
    if (i < DH * DO) {
        float v = W2[i];
        __half h = __float2half_rn(v);
        g_w2h[i] = h;
        g_w2l[i] = __float2half_rn(v - __half2float(h));
    }
}

__global__ __launch_bounds__(1024) void k_p1() {
    __shared__ int ws[32];
    int t = threadIdx.x, idx = blockIdx.x * 1024 + t;
    int v = (idx < NN) ? g_ecnt[idx] : 0;
    if (idx < NN) g_dinv[idx] = rsqrtf((float)(v + 1));
    int s = v;
    #pragma unroll
    for (int o = 16; o; o >>= 1) s += __shfl_xor_sync(0xffffffffu, s, o);
    if ((t & 31) == 0) ws[t >> 5] = s;
    __syncthreads();
    if (t < 32) {
        int x = ws[t];
        #pragma unroll
        for (int o = 16; o; o >>= 1) x += __shfl_xor_sync(0xffffffffu, x, o);
        if (t == 0) g_bsum[blockIdx.x] = x;
    }
}

__global__ void k_p2() {
    __shared__ int ws[4];
    int t = threadIdx.x, lane = t & 31, w = t >> 5;
    int v = (t < NB) ? g_bsum[t] : 0;
    int p = v;
    #pragma unroll
    for (int o = 1; o < 32; o <<= 1) {
        int u = __shfl_up_sync(0xffffffffu, p, o);
        if (lane >= o) p += u;
    }
    if (lane == 31) ws[w] = p;
    __syncthreads();
    int woff = 0;
    #pragma unroll
    for (int k = 0; k < 4; k++) if (k < w) woff += ws[k];
    int incl = p + woff;
    if (t < NB) g_boff[t] = incl - v;
    if (t == NB - 1) g_rowptr[NN] = incl;
}

__global__ __launch_bounds__(1024) void k_p3() {
    __shared__ int ws[32];
    int t = threadIdx.x, lane = t & 31, w = t >> 5;
    int idx = blockIdx.x * 1024 + t;
    int v = (idx < NN) ? g_ecnt[idx] : 0;
    int p = v;
    #pragma unroll
    for (int o = 1; o < 32; o <<= 1) {
        int u = __shfl_up_sync(0xffffffffu, p, o);
        if (lane >= o) p += u;
    }
    if (lane == 31) ws[w] = p;
    __syncthreads();
    if (t < 32) {
        int x = ws[t];
        #pragma unroll
        for (int o = 1; o < 32; o <<= 1) {
            int u = __shfl_up_sync(0xffffffffu, x, o);
            if (lane >= o) x += u;
        }
        ws[t] = x - ws[t];
    }
    __syncthreads();
    if (idx < NN) {
        g_rowptr[idx] = g_boff[blockIdx.x] + ws[w] + p - v;
        g_ecnt[idx] = 0;
    }
}

__global__ void k_fill(const unsigned* __restrict__ ei) {
    int e = blockIdx.x * blockDim.x + threadIdx.x;
    if (e >= NE) return;
    bool is64 = (g_odd_or == 0u);
    int s = (int)(is64 ? ei[2 * (size_t)e]        : ei[e]);
    int d = (int)(is64 ? ei[2 * ((size_t)NE + e)] : ei[(size_t)NE + e]);
    float nrm = g_dinv[s] * g_dinv[d];
    int pos = g_rowptr[d] + atomicAdd(&g_ecnt[d], 1);
    g_epair[pos] = make_int2(s, __float_as_int(nrm));
}

// ---------------------------------------------------------------
// Split-fp16 tensor-core GEMM (m16n8k16, fp32 accum).
// LAYER==0: X = x (fp32, split hi/lo), W = g_w1{h,l}; 3 mmas/tile.  H = g_h16.
// LAYER==1: X = g_agg16 (exact fp16),  W = g_w2{h,l}; 2 mmas/tile.  H = g_h2_16.
__device__ __forceinline__ void mma16(float* c, const unsigned* a, const unsigned* b) {
    asm volatile("mma.sync.aligned.m16n8k16.row.col.f32.f16.f16.f32 "
                 "{%0,%1,%2,%3}, {%4,%5,%6,%7}, {%8,%9}, {%0,%1,%2,%3};"
                 : "+f"(c[0]), "+f"(c[1]), "+f"(c[2]), "+f"(c[3])
                 : "r"(a[0]), "r"(a[1]), "r"(a[2]), "r"(a[3]), "r"(b[0]), "r"(b[1]));
}
__device__ __forceinline__ void ldsm_x4(unsigned* r, unsigned addr) {
    asm volatile("ldmatrix.sync.aligned.m8n8.x4.shared.b16 {%0,%1,%2,%3}, [%4];"
                 : "=r"(r[0]), "=r"(r[1]), "=r"(r[2]), "=r"(r[3]) : "r"(addr));
}
__device__ __forceinline__ void ldsm_x4t(unsigned* r, unsigned addr) {
    asm volatile("ldmatrix.sync.aligned.m8n8.x4.trans.shared.b16 {%0,%1,%2,%3}, [%4];"
                 : "=r"(r[0]), "=r"(r[1]), "=r"(r[2]), "=r"(r[3]) : "r"(addr));
}

template <int BN, int LAYER>
__global__ __launch_bounds__(256) void k_mma(const float* __restrict__ Xext) {
    constexpr int BM = 128, BK = 32;
    constexpr int XS = 40;            // X smem stride (halves): conflict-free ldmatrix
    constexpr int WS = BN + 8;        // W smem stride (halves): conflict-free ldmatrix
    constexpr int NT = BN / 16;       // 8x8 n-tiles per warp (8 or 4)

    __shared__ alignas(16) __half XsH[BM * XS];
    __shared__ alignas(16) __half XsL[LAYER == 0 ? BM * XS : 8];
    __shared__ alignas(16) __half WsH[BK * WS];
    __shared__ alignas(16) __half WsL[BK * WS];

    const __half* Wh = (LAYER == 0) ? g_w1h : g_w2h;
    const __half* Wl = (LAYER == 0) ? g_w1l : g_w2l;
    __half* H = (LAYER == 0) ? g_h16 : g_h2_16;

    int tid = threadIdx.x;
    int lane = tid & 31, wid = tid >> 5;
    int wm = (wid & 3) * 32;          // warp m offset (4 m-warps)
    int wn = (wid >> 2) * (BN / 2);   // warp n offset (2 n-warps)
    int row0 = blockIdx.x * BM;

    unsigned xh_base = (unsigned)__cvta_generic_to_shared(XsH);
    unsigned xl_base = (unsigned)__cvta_generic_to_shared(XsL);
    unsigned wh_base = (unsigned)__cvta_generic_to_shared(WsH);
    unsigned wl_base = (unsigned)__cvta_generic_to_shared(WsL);

    float acc[2][NT][4];
    #pragma unroll
    for (int mt = 0; mt < 2; mt++)
        #pragma unroll
        for (int nt = 0; nt < NT; nt++)
            #pragma unroll
            for (int q = 0; q < 4; q++) acc[mt][nt][q] = 0.f;

    // ldmatrix lane addressing (halves offsets)
    int a_row = lane & 15, a_col = (lane >> 4) * 8;                    // A x4
    int b_row = (lane & 7) + ((lane >> 3) & 1) * 8;                    // B x4.trans
    int b_col = (lane >> 4) * 8;

    for (int kc = 0; kc < 128; kc += BK) {
        // ---- X tile: BM x BK ----
        #pragma unroll
        for (int f = tid; f < BM * (BK / 4); f += 256) {
            int rr = f >> 3, kq = (f & 7) * 4;
            int grow = row0 + rr;
            if (LAYER == 0) {
                float4 v = make_float4(0.f, 0.f, 0.f, 0.f);
                if (grow < NN) v = *(const float4*)(Xext + (size_t)grow * 128 + kc + kq);
                __half h0 = __float2half_rn(v.x), h1 = __float2half_rn(v.y);
                __half h2 = __float2half_rn(v.z), h3 = __float2half_rn(v.w);
                __half l0 = __float2half_rn(v.x - __half2float(h0));
                __half l1 = __float2half_rn(v.y - __half2float(h1));
                __half l2 = __float2half_rn(v.z - __half2float(h2));
                __half l3 = __float2half_rn(v.w - __half2float(h3));
                __half2 H0 = __halves2half2(h0, h1), H1 = __halves2half2(h2, h3);
                __half2 L0 = __halves2half2(l0, l1), L1 = __halves2half2(l2, l3);
                *(uint2*)(XsH + rr * XS + kq) =
                    make_uint2(*(unsigned*)&H0, *(unsigned*)&H1);
                *(uint2*)(XsL + rr * XS + kq) =
                    make_uint2(*(unsigned*)&L0, *(unsigned*)&L1);
            } else {
                uint2 u = make_uint2(0u, 0u);
                if (grow < NN) u = *(const uint2*)(g_agg16 + (size_t)grow * 128 + kc + kq);
                *(uint2*)(XsH + rr * XS + kq) = u;
            }
        }
        // ---- W tile: BK x BN (hi+lo planes, uint4 = 8 halves) ----
        #pragma unroll
        for (int f = tid; f < BK * (BN / 8); f += 256) {
            int kk = f / (BN / 8), nq = (f % (BN / 8)) * 8;
            *(uint4*)(WsH + kk * WS + nq) = *(const uint4*)(Wh + (size_t)(kc + kk) * BN + nq);
            *(uint4*)(WsL + kk * WS + nq) = *(const uint4*)(Wl + (size_t)(kc + kk) * BN + nq);
        }
        __syncthreads();

        #pragma unroll
        for (int k16 = 0; k16 < BK; k16 += 16) {
            unsigned aH[2][4], aL[2][4];
            #pragma unroll
            for (int mt = 0; mt < 2; mt++) {
                unsigned off = (unsigned)(((wm + mt * 16 + a_row) * XS + k16 + a_col) * 2);
                ldsm_x4(aH[mt], xh_base + off);
                if (LAYER == 0) ldsm_x4(aL[mt], xl_base + off);
            }
            #pragma unroll
            for (int np = 0; np < NT / 2; np++) {     // pairs of n-tiles
                unsigned off = (unsigned)(((k16 + b_row) * WS + wn + np * 16 + b_col) * 2);
                unsigned bh[4], bl[4];
                ldsm_x4t(bh, wh_base + off);
                ldsm_x4t(bl, wl_base + off);
                #pragma unroll
                for (int h = 0; h < 2; h++) {         // the two n-tiles in the pair
                    int nt = np * 2 + h;
                    #pragma unroll
                    for (int mt = 0; mt < 2; mt++) {
                        if (LAYER == 0) mma16(acc[mt][nt], aL[mt], bh + 2 * h);
                        mma16(acc[mt][nt], aH[mt], bl + 2 * h);
                        mma16(acc[mt][nt], aH[mt], bh + 2 * h);
                    }
                }
            }
        }
        __syncthreads();
    }

    // epilogue: fp16 store
    int g = lane >> 2, r = lane & 3;
    #pragma unroll
    for (int mt = 0; mt < 2; mt++) {
        int rA = row0 + wm + mt * 16 + g;
        #pragma unroll
        for (int nt = 0; nt < NT; nt++) {
            int col = wn + nt * 8 + 2 * r;
            if (rA < NN)
                *(__half2*)(H + (size_t)rA * BN + col) =
                    __floats2half2_rn(acc[mt][nt][0], acc[mt][nt][1]);
            if (rA + 8 < NN)
                *(__half2*)(H + (size_t)(rA + 8) * BN + col) =
                    __floats2half2_rn(acc[mt][nt][2], acc[mt][nt][3]);
        }
    }
}

// ---------------------------------------------------------------
__device__ __forceinline__ float elu1(float x) { return x > 0.f ? x : expm1f(x); }

__device__ __forceinline__ void acc128(float* acc, uint2 u, float n) {
    float2 f0 = __half22float2(*reinterpret_cast<__half2*>(&u.x));
    float2 f1 = __half22float2(*reinterpret_cast<__half2*>(&u.y));
    acc[0] += f0.x * n; acc[1] += f0.y * n;
    acc[2] += f1.x * n; acc[3] += f1.y * n;
}
__device__ __forceinline__ void acc64(float* acc, unsigned u, float n) {
    float2 f0 = __half22float2(*reinterpret_cast<__half2*>(&u));
    acc[0] += f0.x * n; acc[1] += f0.y * n;
}

template <int D>
__global__ void k_agg(const float* __restrict__ bias, float* __restrict__ outp) {
    int node = (blockIdx.x * blockDim.x + threadIdx.x) >> 5;
    if (node >= NN) return;
    int lane = threadIdx.x & 31;
    constexpr int VL = D / 32;

    const __half* H = (D == DH) ? g_h16 : g_h2_16;

    float acc[VL];
    #pragma unroll
    for (int k = 0; k < VL; k++) acc[k] = 0.f;

    int beg = g_rowptr[node], end = g_rowptr[node + 1];
    int j = beg;
    for (; j + 8 <= end; j += 8) {
        int2 p[8];
        #pragma unroll
        for (int i = 0; i < 8; i++) p[i] = __ldg(&g_epair[j + i]);
        if (D == DH) {
            uint2 u[8];
            #pragma unroll
            for (int i = 0; i < 8; i++)
                u[i] = __ldg((const uint2*)(H + (size_t)p[i].x * D) + lane);
            #pragma unroll
            for (int i = 0; i < 8; i++)
                acc128(acc, u[i], __int_as_float(p[i].y));
        } else {
            unsigned u[8];
            #pragma unroll
            for (int i = 0; i < 8; i++)
                u[i] = __ldg((const unsigned*)(H + (size_t)p[i].x * D) + lane);
            #pragma unroll
            for (int i = 0; i < 8; i++)
                acc64(acc, u[i], __int_as_float(p[i].y));
        }
    }
    for (; j < end; j++) {
        int2 p = __ldg(&g_epair[j]);
        float n = __int_as_float(p.y);
        if (D == DH) {
            uint2 u = __ldg((const uint2*)(H + (size_t)p.x * D) + lane);
            acc128(acc, u, n);
        } else {
            unsigned u = __ldg((const unsigned*)(H + (size_t)p.x * D) + lane);
            acc64(acc, u, n);
        }
    }

    float di = g_dinv[node], d2 = di * di;
    if (D == DH) {
        uint2 us = __ldg((const uint2*)(H + (size_t)node * D) + lane);
        float hv[4] = {0.f, 0.f, 0.f, 0.f};
        acc128(hv, us, d2);
        float4 bv = *(const float4*)(bias + lane * 4);
        float r0 = elu1(acc[0] + hv[0] + bv.x);
        float r1 = elu1(acc[1] + hv[1] + bv.y);
        float r2 = elu1(acc[2] + hv[2] + bv.z);
        float r3 = elu1(acc[3] + hv[3] + bv.w);
        __half2 o0 = __floats2half2_rn(r0, r1);
        __half2 o1 = __floats2half2_rn(r2, r3);
        *((uint2*)(g_agg16 + (size_t)node * D) + lane) =
            make_uint2(*reinterpret_cast<unsigned*>(&o0), *reinterpret_cast<unsigned*>(&o1));
    } else {
        unsigned us = __ldg((const unsigned*)(H + (size_t)node * D) + lane);
        float hv[2] = {0.f, 0.f};
        acc64(hv, us, d2);
        float2 bv = *(const float2*)(bias + lane * 2);
        float2 rr;
        rr.x = elu1(acc[0] + hv[0] + bv.x);
        rr.y = elu1(acc[1] + hv[1] + bv.y);
        *(float2*)(outp + (size_t)node * D + lane * 2) = rr;
    }
}

// ---------------------------------------------------------------
extern "C" void kernel_launch(void* const* d_in, const int* in_sizes, int n_in,
                              void* d_out, int out_size) {
    const float*    x  = (const float*)d_in[0];
    const unsigned* ei = (const unsigned*)d_in[1];
    const float*    W1 = (const float*)d_in[2];
    const float*    b1 = (const float*)d_in[3];
    const float*    W2 = (const float*)d_in[4];
    const float*    b2 = (const float*)d_in[5];
    float*          out = (float*)d_out;

    k_init  <<<(NN + 255) / 256, 256>>>(ei);            // 0
    k_count <<<(NE + 255) / 256, 256>>>(ei);            // 1
    k_wsplit<<<64, 256>>>(W1, W2);                      // 2
    k_mma<DH, 0><<<(NN + 127) / 128, 256>>>(x);         // 3 (profiled slot)
    k_p1    <<<NB, 1024>>>();                           // 4
    k_p2    <<<1, 128>>>();                             // 5
    k_p3    <<<NB, 1024>>>();                           // 6
    k_fill  <<<(NE + 255) / 256, 256>>>(ei);            // 7

    k_agg<DH><<<(NN * 32 + 255) / 256, 256>>>(b1, nullptr);   // 8
    k_mma<DO, 1><<<(NN + 127) / 128, 256>>>(nullptr);         // 9
    k_agg<DO><<<(NN * 32 + 255) / 256, 256>>>(b2, out);       // 10

    (void)in_sizes; (void)n_in; (void)out_size;
}

// round 9
// speedup vs baseline: 1.0042x; 1.0038x over previous
#include <cuda_runtime.h>
#include <cuda_fp16.h>
#include <math.h>

#define NN 100000
#define NE 1600000
#define DH 128
#define DO 64
#define NB 98   // ceil(NN/1024)

// ---- scratch (static device globals; no allocation allowed) ----
__device__ __half g_h16  [(size_t)NN * DH]; // layer1 gemm output (fp16)
__device__ __half g_h2_16[(size_t)NN * DO]; // layer2 gemm output (fp16)
__device__ __half g_agg16[(size_t)NN * DH]; // layer1 activated output (fp16)
__device__ __half g_w1h[DH * DH], g_w1l[DH * DH];
__device__ __half g_w2h[DH * DO], g_w2l[DH * DO];
__device__ float  g_dinv [NN];
__device__ int    g_ecnt [NN];
__device__ int    g_rowptr[NN + 1];
__device__ int    g_bsum[NB];
__device__ int    g_boff[NB];
__device__ int2   g_epair[NE];
__device__ unsigned g_odd_or;               // 0 => edge_index is int64

// ---------------------------------------------------------------
__global__ void k_init(const unsigned* __restrict__ ei) {
    int i = blockIdx.x * blockDim.x + threadIdx.x;
    if (i < NN) g_ecnt[i] = 0;
    if (i < 65536) {
        unsigned v = ei[2 * i + 1];
        #pragma unroll
        for (int o = 16; o; o >>= 1) v |= __shfl_xor_sync(0xffffffffu, v, o);
        if ((threadIdx.x & 31) == 0 && v) atomicOr(&g_odd_or, v);
    }
}

__global__ void k_count(const unsigned* __restrict__ ei) {
    int e = blockIdx.x * blockDim.x + threadIdx.x;
    if (e >= NE) return;
    bool is64 = (g_odd_or == 0u);
    int d = (int)(is64 ? ei[2 * ((size_t)NE + e)] : ei[(size_t)NE + e]);
    atomicAdd(&g_ecnt[d], 1);
}

// W hi/lo fp16 splits (once).
__global__ void k_wsplit(const float* __restrict__ W1, const float* __restrict__ W2) {
    int i = blockIdx.x * blockDim.x + threadIdx.x;
    if (i < DH * DH) {
        float v = W1[i];
        __half h = __float2half_rn(v);
        g_w1h[i] = h;
        g_w1l[i] = __float2half_rn(v - __half2float(h));
    }
    if (i < DH * DO) {
        float v = W2[i];
        __half h = __float2half_rn(v);
        g_w2h[i] = h;
        g_w2l[i] = __float2half_rn(v - __half2float(h));
    }
}

__global__ __launch_bounds__(1024) void k_p1() {
    __shared__ int ws[32];
    int t = threadIdx.x, idx = blockIdx.x * 1024 + t;
    int v = (idx < NN) ? g_ecnt[idx] : 0;
    if (idx < NN) g_dinv[idx] = rsqrtf((float)(v + 1));
    int s = v;
    #pragma unroll
    for (int o = 16; o; o >>= 1) s += __shfl_xor_sync(0xffffffffu, s, o);
    if ((t & 31) == 0) ws[t >> 5] = s;
    __syncthreads();
    if (t < 32) {
        int x = ws[t];
        #pragma unroll
        for (int o = 16; o; o >>= 1) x += __shfl_xor_sync(0xffffffffu, x, o);
        if (t == 0) g_bsum[blockIdx.x] = x;
    }
}

__global__ void k_p2() {
    __shared__ int ws[4];
    int t = threadIdx.x, lane = t & 31, w = t >> 5;
    int v = (t < NB) ? g_bsum[t] : 0;
    int p = v;
    #pragma unroll
    for (int o = 1; o < 32; o <<= 1) {
        int u = __shfl_up_sync(0xffffffffu, p, o);
        if (lane >= o) p += u;
    }
    if (lane == 31) ws[w] = p;
    __syncthreads();
    int woff = 0;
    #pragma unroll
    for (int k = 0; k < 4; k++) if (k < w) woff += ws[k];
    int incl = p + woff;
    if (t < NB) g_boff[t] = incl - v;
    if (t == NB - 1) g_rowptr[NN] = incl;
}

__global__ __launch_bounds__(1024) void k_p3() {
    __shared__ int ws[32];
    int t = threadIdx.x, lane = t & 31, w = t >> 5;
    int idx = blockIdx.x * 1024 + t;
    int v = (idx < NN) ? g_ecnt[idx] : 0;
    int p = v;
    #pragma unroll
    for (int o = 1; o < 32; o <<= 1) {
        int u = __shfl_up_sync(0xffffffffu, p, o);
        if (lane >= o) p += u;
    }
    if (lane == 31) ws[w] = p;
    __syncthreads();
    if (t < 32) {
        int x = ws[t];
        #pragma unroll
        for (int o = 1; o < 32; o <<= 1) {
            int u = __shfl_up_sync(0xffffffffu, x, o);
            if (lane >= o) x += u;
        }
        ws[t] = x - ws[t];
    }
    __syncthreads();
    if (idx < NN) {
        g_rowptr[idx] = g_boff[blockIdx.x] + ws[w] + p - v;
        g_ecnt[idx] = 0;
    }
}

__global__ void k_fill(const unsigned* __restrict__ ei) {
    int e = blockIdx.x * blockDim.x + threadIdx.x;
    if (e >= NE) return;
    bool is64 = (g_odd_or == 0u);
    int s = (int)(is64 ? ei[2 * (size_t)e]        : ei[e]);
    int d = (int)(is64 ? ei[2 * ((size_t)NE + e)] : ei[(size_t)NE + e]);
    float nrm = g_dinv[s] * g_dinv[d];
    int pos = g_rowptr[d] + atomicAdd(&g_ecnt[d], 1);
    g_epair[pos] = make_int2(s, __float_as_int(nrm));
}

// ---------------------------------------------------------------
// Split-fp16 tensor-core GEMM (m16n8k16, fp32 accum).
// LAYER==0: X = x (fp32, split hi/lo), W = g_w1{h,l}; 3 mmas/tile.  H = g_h16.
// LAYER==1: X = g_agg16 (exact fp16),  W = g_w2{h,l}; 2 mmas/tile.  H = g_h2_16.
__device__ __forceinline__ void mma16(float* c, const unsigned* a, const unsigned* b) {
    asm volatile("mma.sync.aligned.m16n8k16.row.col.f32.f16.f16.f32 "
                 "{%0,%1,%2,%3}, {%4,%5,%6,%7}, {%8,%9}, {%0,%1,%2,%3};"
                 : "+f"(c[0]), "+f"(c[1]), "+f"(c[2]), "+f"(c[3])
                 : "r"(a[0]), "r"(a[1]), "r"(a[2]), "r"(a[3]), "r"(b[0]), "r"(b[1]));
}
__device__ __forceinline__ void ldsm_x4(unsigned* r, unsigned addr) {
    asm volatile("ldmatrix.sync.aligned.m8n8.x4.shared.b16 {%0,%1,%2,%3}, [%4];"
                 : "=r"(r[0]), "=r"(r[1]), "=r"(r[2]), "=r"(r[3]) : "r"(addr));
}
__device__ __forceinline__ void ldsm_x4t(unsigned* r, unsigned addr) {
    asm volatile("ldmatrix.sync.aligned.m8n8.x4.trans.shared.b16 {%0,%1,%2,%3}, [%4];"
                 : "=r"(r[0]), "=r"(r[1]), "=r"(r[2]), "=r"(r[3]) : "r"(addr));
}

template <int BN, int LAYER>
__global__ __launch_bounds__(256) void k_mma(const float* __restrict__ Xext) {
    constexpr int BM = 128, BK = 32;
    constexpr int XS = 40;            // X smem stride (halves): conflict-free ldmatrix
    constexpr int WS = BN + 8;        // W smem stride (halves): conflict-free ldmatrix
    constexpr int NT = BN / 16;       // 8x8 n-tiles per warp (8 or 4)

    __shared__ alignas(16) __half XsH[BM * XS];
    __shared__ alignas(16) __half XsL[LAYER == 0 ? BM * XS : 8];
    __shared__ alignas(16) __half WsH[BK * WS];
    __shared__ alignas(16) __half WsL[BK * WS];

    const __half* Wh = (LAYER == 0) ? g_w1h : g_w2h;
    const __half* Wl = (LAYER == 0) ? g_w1l : g_w2l;
    __half* H = (LAYER == 0) ? g_h16 : g_h2_16;

    int tid = threadIdx.x;
    int lane = tid & 31, wid = tid >> 5;
    int wm = (wid & 3) * 32;          // warp m offset (4 m-warps)
    int wn = (wid >> 2) * (BN / 2);   // warp n offset (2 n-warps)
    int row0 = blockIdx.x * BM;

    unsigned xh_base = (unsigned)__cvta_generic_to_shared(XsH);
    unsigned xl_base = (unsigned)__cvta_generic_to_shared(XsL);
    unsigned wh_base = (unsigned)__cvta_generic_to_shared(WsH);
    unsigned wl_base = (unsigned)__cvta_generic_to_shared(WsL);

    float acc[2][NT][4];
    #pragma unroll
    for (int mt = 0; mt < 2; mt++)
        #pragma unroll
        for (int nt = 0; nt < NT; nt++)
            #pragma unroll
            for (int q = 0; q < 4; q++) acc[mt][nt][q] = 0.f;

    // ldmatrix lane addressing (halves offsets)
    int a_row = lane & 15, a_col = (lane >> 4) * 8;                    // A x4
    int b_row = (lane & 7) + ((lane >> 3) & 1) * 8;                    // B x4.trans
    int b_col = (lane >> 4) * 8;

    for (int kc = 0; kc < 128; kc += BK) {
        // ---- X tile: BM x BK ----
        #pragma unroll
        for (int f = tid; f < BM * (BK / 4); f += 256) {
            int rr = f >> 3, kq = (f & 7) * 4;
            int grow = row0 + rr;
            if (LAYER == 0) {
                float4 v = make_float4(0.f, 0.f, 0.f, 0.f);
                if (grow < NN) v = *(const float4*)(Xext + (size_t)grow * 128 + kc + kq);
                __half h0 = __float2half_rn(v.x), h1 = __float2half_rn(v.y);
                __half h2 = __float2half_rn(v.z), h3 = __float2half_rn(v.w);
                __half l0 = __float2half_rn(v.x - __half2float(h0));
                __half l1 = __float2half_rn(v.y - __half2float(h1));
                __half l2 = __float2half_rn(v.z - __half2float(h2));
                __half l3 = __float2half_rn(v.w - __half2float(h3));
                __half2 H0 = __halves2half2(h0, h1), H1 = __halves2half2(h2, h3);
                __half2 L0 = __halves2half2(l0, l1), L1 = __halves2half2(l2, l3);
                *(uint2*)(XsH + rr * XS + kq) =
                    make_uint2(*(unsigned*)&H0, *(unsigned*)&H1);
                *(uint2*)(XsL + rr * XS + kq) =
                    make_uint2(*(unsigned*)&L0, *(unsigned*)&L1);
            } else {
                uint2 u = make_uint2(0u, 0u);
                if (grow < NN) u = *(const uint2*)(g_agg16 + (size_t)grow * 128 + kc + kq);
                *(uint2*)(XsH + rr * XS + kq) = u;
            }
        }
        // ---- W tile: BK x BN (hi+lo planes, uint4 = 8 halves) ----
        #pragma unroll
        for (int f = tid; f < BK * (BN / 8); f += 256) {
            int kk = f / (BN / 8), nq = (f % (BN / 8)) * 8;
            *(uint4*)(WsH + kk * WS + nq) = *(const uint4*)(Wh + (size_t)(kc + kk) * BN + nq);
            *(uint4*)(WsL + kk * WS + nq) = *(const uint4*)(Wl + (size_t)(kc + kk) * BN + nq);
        }
        __syncthreads();

        #pragma unroll
        for (int k16 = 0; k16 < BK; k16 += 16) {
            unsigned aH[2][4], aL[2][4];
            #pragma unroll
            for (int mt = 0; mt < 2; mt++) {
                unsigned off = (unsigned)(((wm + mt * 16 + a_row) * XS + k16 + a_col) * 2);
                ldsm_x4(aH[mt], xh_base + off);
                if (LAYER == 0) ldsm_x4(aL[mt], xl_base + off);
            }
            #pragma unroll
            for (int np = 0; np < NT / 2; np++) {     // pairs of n-tiles
                unsigned off = (unsigned)(((k16 + b_row) * WS + wn + np * 16 + b_col) * 2);
                unsigned bh[4], bl[4];
                ldsm_x4t(bh, wh_base + off);
                ldsm_x4t(bl, wl_base + off);
                #pragma unroll
                for (int h = 0; h < 2; h++) {         // the two n-tiles in the pair
                    int nt = np * 2 + h;
                    #pragma unroll
                    for (int mt = 0; mt < 2; mt++) {
                        if (LAYER == 0) mma16(acc[mt][nt], aL[mt], bh + 2 * h);
                        mma16(acc[mt][nt], aH[mt], bl + 2 * h);
                        mma16(acc[mt][nt], aH[mt], bh + 2 * h);
                    }
                }
            }
        }
        __syncthreads();
    }

    // epilogue: fp16 store
    int g = lane >> 2, r = lane & 3;
    #pragma unroll
    for (int mt = 0; mt < 2; mt++) {
        int rA = row0 + wm + mt * 16 + g;
        #pragma unroll
        for (int nt = 0; nt < NT; nt++) {
            int col = wn + nt * 8 + 2 * r;
            if (rA < NN)
                *(__half2*)(H + (size_t)rA * BN + col) =
                    __floats2half2_rn(acc[mt][nt][0], acc[mt][nt][1]);
            if (rA + 8 < NN)
                *(__half2*)(H + (size_t)(rA + 8) * BN + col) =
                    __floats2half2_rn(acc[mt][nt][2], acc[mt][nt][3]);
        }
    }
}

// ---------------------------------------------------------------
__device__ __forceinline__ float elu1(float x) { return x > 0.f ? x : expm1f(x); }

__device__ __forceinline__ void acc128(float* acc, uint2 u, float n) {
    float2 f0 = __half22float2(*reinterpret_cast<__half2*>(&u.x));
    float2 f1 = __half22float2(*reinterpret_cast<__half2*>(&u.y));
    acc[0] += f0.x * n; acc[1] += f0.y * n;
    acc[2] += f1.x * n; acc[3] += f1.y * n;
}
__device__ __forceinline__ void acc64(float* acc, unsigned u, float n) {
    float2 f0 = __half22float2(*reinterpret_cast<__half2*>(&u));
    acc[0] += f0.x * n; acc[1] += f0.y * n;
}

template <int D>
__global__ void k_agg(const float* __restrict__ bias, float* __restrict__ outp) {
    int node = (blockIdx.x * blockDim.x + threadIdx.x) >> 5;
    if (node >= NN) return;
    int lane = threadIdx.x & 31;
    constexpr int VL = D / 32;

    const __half* H = (D == DH) ? g_h16 : g_h2_16;

    float acc[VL];
    #pragma unroll
    for (int k = 0; k < VL; k++) acc[k] = 0.f;

    int beg = g_rowptr[node], end = g_rowptr[node + 1];
    int j = beg;
    for (; j + 8 <= end; j += 8) {
        int2 p[8];
        #pragma unroll
        for (int i = 0; i < 8; i++) p[i] = __ldg(&g_epair[j + i]);
        if (D == DH) {
            uint2 u[8];
            #pragma unroll
            for (int i = 0; i < 8; i++)
                u[i] = __ldg((const uint2*)(H + (size_t)p[i].x * D) + lane);
            #pragma unroll
            for (int i = 0; i < 8; i++)
                acc128(acc, u[i], __int_as_float(p[i].y));
        } else {
            unsigned u[8];
            #pragma unroll
            for (int i = 0; i < 8; i++)
                u[i] = __ldg((const unsigned*)(H + (size_t)p[i].x * D) + lane);
            #pragma unroll
            for (int i = 0; i < 8; i++)
                acc64(acc, u[i], __int_as_float(p[i].y));
        }
    }
    for (; j < end; j++) {
        int2 p = __ldg(&g_epair[j]);
        float n = __int_as_float(p.y);
        if (D == DH) {
            uint2 u = __ldg((const uint2*)(H + (size_t)p.x * D) + lane);
            acc128(acc, u, n);
        } else {
            unsigned u = __ldg((const unsigned*)(H + (size_t)p.x * D) + lane);
            acc64(acc, u, n);
        }
    }

    float di = g_dinv[node], d2 = di * di;
    if (D == DH) {
        uint2 us = __ldg((const uint2*)(H + (size_t)node * D) + lane);
        float hv[4] = {0.f, 0.f, 0.f, 0.f};
        acc128(hv, us, d2);
        float4 bv = *(const float4*)(bias + lane * 4);
        float r0 = elu1(acc[0] + hv[0] + bv.x);
        float r1 = elu1(acc[1] + hv[1] + bv.y);
        float r2 = elu1(acc[2] + hv[2] + bv.z);
        float r3 = elu1(acc[3] + hv[3] + bv.w);
        __half2 o0 = __floats2half2_rn(r0, r1);
        __half2 o1 = __floats2half2_rn(r2, r3);
        *((uint2*)(g_agg16 + (size_t)node * D) + lane) =
            make_uint2(*reinterpret_cast<unsigned*>(&o0), *reinterpret_cast<unsigned*>(&o1));
    } else {
        unsigned us = __ldg((const unsigned*)(H + (size_t)node * D) + lane);
        float hv[2] = {0.f, 0.f};
        acc64(hv, us, d2);
        float2 bv = *(const float2*)(bias + lane * 2);
        float2 rr;
        rr.x = elu1(acc[0] + hv[0] + bv.x);
        rr.y = elu1(acc[1] + hv[1] + bv.y);
        *(float2*)(outp + (size_t)node * D + lane * 2) = rr;
    }
}

// ---------------------------------------------------------------
extern "C" void kernel_launch(void* const* d_in, const int* in_sizes, int n_in,
                              void* d_out, int out_size) {
    const float*    x  = (const float*)d_in[0];
    const unsigned* ei = (const unsigned*)d_in[1];
    const float*    W1 = (const float*)d_in[2];
    const float*    b1 = (const float*)d_in[3];
    const float*    W2 = (const float*)d_in[4];
    const float*    b2 = (const float*)d_in[5];
    float*          out = (float*)d_out;

    k_init  <<<(NN + 255) / 256, 256>>>(ei);            // 0
    k_count <<<(NE + 255) / 256, 256>>>(ei);            // 1
    k_wsplit<<<64, 256>>>(W1, W2);                      // 2
    k_mma<DH, 0><<<(NN + 127) / 128, 256>>>(x);         // 3 (profiled slot)
    k_p1    <<<NB, 1024>>>();                           // 4
    k_p2    <<<1, 128>>>();                             // 5
    k_p3    <<<NB, 1024>>>();                           // 6
    k_fill  <<<(NE + 255) / 256, 256>>>(ei);            // 7

    k_agg<DH><<<(NN * 32 + 255) / 256, 256>>>(b1, nullptr);   // 8
    k_mma<DO, 1><<<(NN + 127) / 128, 256>>>(nullptr);         // 9
    k_agg<DO><<<(NN * 32 + 255) / 256, 256>>>(b2, out);       // 10

    (void)in_sizes; (void)n_in; (void)out_size;
}

// round 10
// speedup vs baseline: 1.0056x; 1.0014x over previous
#include <cuda_runtime.h>
#include <cuda_fp16.h>
#include <math.h>

#define NN 100000
#define NE 1600000
#define DH 128
#define DO 64
#define NB 98   // ceil(NN/1024)

// ---- scratch (static device globals; no allocation allowed) ----
__device__ __half g_h16  [(size_t)NN * DH]; // layer1 gemm output (fp16)
__device__ __half g_h2_16[(size_t)NN * DO]; // layer2 gemm output (fp16)
__device__ __half g_agg16[(size_t)NN * DH]; // layer1 activated output (fp16)
__device__ __half g_w1h[DH * DH], g_w1l[DH * DH];
__device__ __half g_w2h[DH * DO], g_w2l[DH * DO];
__device__ float  g_dinv [NN];
__device__ int    g_ecnt [NN];
__device__ int    g_rowptr[NN + 1];
__device__ int    g_bsum[NB];
__device__ int    g_boff[NB];
__device__ int2   g_epair[NE];
__device__ unsigned g_odd_or;               // 0 => edge_index is int64

// ---------------------------------------------------------------
__global__ void k_init(const unsigned* __restrict__ ei) {
    int i = blockIdx.x * blockDim.x + threadIdx.x;
    if (i < NN) g_ecnt[i] = 0;
    if (i < 65536) {
        unsigned v = ei[2 * i + 1];
        #pragma unroll
        for (int o = 16; o; o >>= 1) v |= __shfl_xor_sync(0xffffffffu, v, o);
        if ((threadIdx.x & 31) == 0 && v) atomicOr(&g_odd_or, v);
    }
}

__global__ void k_count(const unsigned* __restrict__ ei) {
    int e = blockIdx.x * blockDim.x + threadIdx.x;
    if (e >= NE) return;
    bool is64 = (g_odd_or == 0u);
    int d = (int)(is64 ? ei[2 * ((size_t)NE + e)] : ei[(size_t)NE + e]);
    atomicAdd(&g_ecnt[d], 1);
}

// W hi/lo fp16 splits (once).
__global__ void k_wsplit(const float* __restrict__ W1, const float* __restrict__ W2) {
    int i = blockIdx.x * blockDim.x + threadIdx.x;
    if (i < DH * DH) {
        float v = W1[i];
        __half h = __float2half_rn(v);
        g_w1h[i] = h;
        g_w1l[i] = __float2half_rn(v - __half2float(h));
    }
    if (i < DH * DO) {
        float v = W2[i];
        __half h = __float2half_rn(v);
        g_w2h[i] = h;
        g_w2l[i] = __float2half_rn(v - __half2float(h));
    }
}

__global__ __launch_bounds__(1024) void k_p1() {
    __shared__ int ws[32];
    int t = threadIdx.x, idx = blockIdx.x * 1024 + t;
    int v = (idx < NN) ? g_ecnt[idx] : 0;
    if (idx < NN) g_dinv[idx] = rsqrtf((float)(v + 1));
    int s = v;
    #pragma unroll
    for (int o = 16; o; o >>= 1) s += __shfl_xor_sync(0xffffffffu, s, o);
    if ((t & 31) == 0) ws[t >> 5] = s;
    __syncthreads();
    if (t < 32) {
        int x = ws[t];
        #pragma unroll
        for (int o = 16; o; o >>= 1) x += __shfl_xor_sync(0xffffffffu, x, o);
        if (t == 0) g_bsum[blockIdx.x] = x;
    }
}

__global__ void k_p2() {
    __shared__ int ws[4];
    int t = threadIdx.x, lane = t & 31, w = t >> 5;
    int v = (t < NB) ? g_bsum[t] : 0;
    int p = v;
    #pragma unroll
    for (int o = 1; o < 32; o <<= 1) {
        int u = __shfl_up_sync(0xffffffffu, p, o);
        if (lane >= o) p += u;
    }
    if (lane == 31) ws[w] = p;
    __syncthreads();
    int woff = 0;
    #pragma unroll
    for (int k = 0; k < 4; k++) if (k < w) woff += ws[k];
    int incl = p + woff;
    if (t < NB) g_boff[t] = incl - v;
    if (t == NB - 1) g_rowptr[NN] = incl;
}

__global__ __launch_bounds__(1024) void k_p3() {
    __shared__ int ws[32];
    int t = threadIdx.x, lane = t & 31, w = t >> 5;
    int idx = blockIdx.x * 1024 + t;
    int v = (idx < NN) ? g_ecnt[idx] : 0;
    int p = v;
    #pragma unroll
    for (int o = 1; o < 32; o <<= 1) {
        int u = __shfl_up_sync(0xffffffffu, p, o);
        if (lane >= o) p += u;
    }
    if (lane == 31) ws[w] = p;
    __syncthreads();
    if (t < 32) {
        int x = ws[t];
        #pragma unroll
        for (int o = 1; o < 32; o <<= 1) {
            int u = __shfl_up_sync(0xffffffffu, x, o);
            if (lane >= o) x += u;
        }
        ws[t] = x - ws[t];
    }
    __syncthreads();
    if (idx < NN) {
        g_rowptr[idx] = g_boff[blockIdx.x] + ws[w] + p - v;
        g_ecnt[idx] = 0;
    }
}

__global__ void k_fill(const unsigned* __restrict__ ei) {
    int e = blockIdx.x * blockDim.x + threadIdx.x;
    if (e >= NE) return;
    bool is64 = (g_odd_or == 0u);
    int s = (int)(is64 ? ei[2 * (size_t)e]        : ei[e]);
    int d = (int)(is64 ? ei[2 * ((size_t)NE + e)] : ei[(size_t)NE + e]);
    float nrm = g_dinv[s] * g_dinv[d];
    int pos = g_rowptr[d] + atomicAdd(&g_ecnt[d], 1);
    g_epair[pos] = make_int2(s, __float_as_int(nrm));
}

// ---------------------------------------------------------------
// Split-fp16 tensor-core GEMM (m16n8k16, fp32 accum).
// LAYER==0: X = x (fp32, split hi/lo), W = g_w1{h,l}; 3 mmas/tile.  H = g_h16.
// LAYER==1: X = g_agg16 (exact fp16),  W = g_w2{h,l}; 2 mmas/tile.  H = g_h2_16.
__device__ __forceinline__ void mma16(float* c, const unsigned* a, const unsigned* b) {
    asm volatile("mma.sync.aligned.m16n8k16.row.col.f32.f16.f16.f32 "
                 "{%0,%1,%2,%3}, {%4,%5,%6,%7}, {%8,%9}, {%0,%1,%2,%3};"
                 : "+f"(c[0]), "+f"(c[1]), "+f"(c[2]), "+f"(c[3])
                 : "r"(a[0]), "r"(a[1]), "r"(a[2]), "r"(a[3]), "r"(b[0]), "r"(b[1]));
}
__device__ __forceinline__ void ldsm_x4(unsigned* r, unsigned addr) {
    asm volatile("ldmatrix.sync.aligned.m8n8.x4.shared.b16 {%0,%1,%2,%3}, [%4];"
                 : "=r"(r[0]), "=r"(r[1]), "=r"(r[2]), "=r"(r[3]) : "r"(addr));
}
__device__ __forceinline__ void ldsm_x4t(unsigned* r, unsigned addr) {
    asm volatile("ldmatrix.sync.aligned.m8n8.x4.trans.shared.b16 {%0,%1,%2,%3}, [%4];"
                 : "=r"(r[0]), "=r"(r[1]), "=r"(r[2]), "=r"(r[3]) : "r"(addr));
}

template <int BN, int LAYER>
__global__ __launch_bounds__(256) void k_mma(const float* __restrict__ Xext) {
    constexpr int BM = 128, BK = 32;
    constexpr int XS = 40;            // X smem stride (halves): conflict-free ldmatrix
    constexpr int WS = BN + 8;        // W smem stride (halves): conflict-free ldmatrix
    constexpr int NT = BN / 16;       // 8x8 n-tiles per warp (8 or 4)

    __shared__ alignas(16) __half XsH[BM * XS];
    __shared__ alignas(16) __half XsL[LAYER == 0 ? BM * XS : 8];
    __shared__ alignas(16) __half WsH[BK * WS];
    __shared__ alignas(16) __half WsL[BK * WS];

    const __half* Wh = (LAYER == 0) ? g_w1h : g_w2h;
    const __half* Wl = (LAYER == 0) ? g_w1l : g_w2l;
    __half* H = (LAYER == 0) ? g_h16 : g_h2_16;

    int tid = threadIdx.x;
    int lane = tid & 31, wid = tid >> 5;
    int wm = (wid & 3) * 32;          // warp m offset (4 m-warps)
    int wn = (wid >> 2) * (BN / 2);   // warp n offset (2 n-warps)
    int row0 = blockIdx.x * BM;

    unsigned xh_base = (unsigned)__cvta_generic_to_shared(XsH);
    unsigned xl_base = (unsigned)__cvta_generic_to_shared(XsL);
    unsigned wh_base = (unsigned)__cvta_generic_to_shared(WsH);
    unsigned wl_base = (unsigned)__cvta_generic_to_shared(WsL);

    float acc[2][NT][4];
    #pragma unroll
    for (int mt = 0; mt < 2; mt++)
        #pragma unroll
        for (int nt = 0; nt < NT; nt++)
            #pragma unroll
            for (int q = 0; q < 4; q++) acc[mt][nt][q] = 0.f;

    // ldmatrix lane addressing (halves offsets)
    int a_row = lane & 15, a_col = (lane >> 4) * 8;                    // A x4
    int b_row = (lane & 7) + ((lane >> 3) & 1) * 8;                    // B x4.trans
    int b_col = (lane >> 4) * 8;

    for (int kc = 0; kc < 128; kc += BK) {
        // ---- X tile: BM x BK ----
        #pragma unroll
        for (int f = tid; f < BM * (BK / 4); f += 256) {
            int rr = f >> 3, kq = (f & 7) * 4;
            int grow = row0 + rr;
            if (LAYER == 0) {
                float4 v = make_float4(0.f, 0.f, 0.f, 0.f);
                if (grow < NN) v = *(const float4*)(Xext + (size_t)grow * 128 + kc + kq);
                __half h0 = __float2half_rn(v.x), h1 = __float2half_rn(v.y);
                __half h2 = __float2half_rn(v.z), h3 = __float2half_rn(v.w);
                __half l0 = __float2half_rn(v.x - __half2float(h0));
                __half l1 = __float2half_rn(v.y - __half2float(h1));
                __half l2 = __float2half_rn(v.z - __half2float(h2));
                __half l3 = __float2half_rn(v.w - __half2float(h3));
                __half2 H0 = __halves2half2(h0, h1), H1 = __halves2half2(h2, h3);
                __half2 L0 = __halves2half2(l0, l1), L1 = __halves2half2(l2, l3);
                *(uint2*)(XsH + rr * XS + kq) =
                    make_uint2(*(unsigned*)&H0, *(unsigned*)&H1);
                *(uint2*)(XsL + rr * XS + kq) =
                    make_uint2(*(unsigned*)&L0, *(unsigned*)&L1);
            } else {
                uint2 u = make_uint2(0u, 0u);
                if (grow < NN) u = *(const uint2*)(g_agg16 + (size_t)grow * 128 + kc + kq);
                *(uint2*)(XsH + rr * XS + kq) = u;
            }
        }
        // ---- W tile: BK x BN (hi+lo planes, uint4 = 8 halves) ----
        #pragma unroll
        for (int f = tid; f < BK * (BN / 8); f += 256) {
            int kk = f / (BN / 8), nq = (f % (BN / 8)) * 8;
            *(uint4*)(WsH + kk * WS + nq) = *(const uint4*)(Wh + (size_t)(kc + kk) * BN + nq);
            *(uint4*)(WsL + kk * WS + nq) = *(const uint4*)(Wl + (size_t)(kc + kk) * BN + nq);
        }
        __syncthreads();

        #pragma unroll
        for (int k16 = 0; k16 < BK; k16 += 16) {
            unsigned aH[2][4], aL[2][4];
            #pragma unroll
            for (int mt = 0; mt < 2; mt++) {
                unsigned off = (unsigned)(((wm + mt * 16 + a_row) * XS + k16 + a_col) * 2);
                ldsm_x4(aH[mt], xh_base + off);
                if (LAYER == 0) ldsm_x4(aL[mt], xl_base + off);
            }
            #pragma unroll
            for (int np = 0; np < NT / 2; np++) {     // pairs of n-tiles
                unsigned off = (unsigned)(((k16 + b_row) * WS + wn + np * 16 + b_col) * 2);
                unsigned bh[4], bl[4];
                ldsm_x4t(bh, wh_base + off);
                ldsm_x4t(bl, wl_base + off);
                #pragma unroll
                for (int h = 0; h < 2; h++) {         // the two n-tiles in the pair
                    int nt = np * 2 + h;
                    #pragma unroll
                    for (int mt = 0; mt < 2; mt++) {
                        if (LAYER == 0) mma16(acc[mt][nt], aL[mt], bh + 2 * h);
                        mma16(acc[mt][nt], aH[mt], bl + 2 * h);
                        mma16(acc[mt][nt], aH[mt], bh + 2 * h);
                    }
                }
            }
        }
        __syncthreads();
    }

    // epilogue: fp16 store
    int g = lane >> 2, r = lane & 3;
    #pragma unroll
    for (int mt = 0; mt < 2; mt++) {
        int rA = row0 + wm + mt * 16 + g;
        #pragma unroll
        for (int nt = 0; nt < NT; nt++) {
            int col = wn + nt * 8 + 2 * r;
            if (rA < NN)
                *(__half2*)(H + (size_t)rA * BN + col) =
                    __floats2half2_rn(acc[mt][nt][0], acc[mt][nt][1]);
            if (rA + 8 < NN)
                *(__half2*)(H + (size_t)(rA + 8) * BN + col) =
                    __floats2half2_rn(acc[mt][nt][2], acc[mt][nt][3]);
        }
    }
}

// ---------------------------------------------------------------
__device__ __forceinline__ float elu1(float x) { return x > 0.f ? x : expm1f(x); }

__device__ __forceinline__ void acc128(float* acc, uint2 u, float n) {
    float2 f0 = __half22float2(*reinterpret_cast<__half2*>(&u.x));
    float2 f1 = __half22float2(*reinterpret_cast<__half2*>(&u.y));
    acc[0] += f0.x * n; acc[1] += f0.y * n;
    acc[2] += f1.x * n; acc[3] += f1.y * n;
}
__device__ __forceinline__ void acc64(float* acc, unsigned u, float n) {
    float2 f0 = __half22float2(*reinterpret_cast<__half2*>(&u));
    acc[0] += f0.x * n; acc[1] += f0.y * n;
}

template <int D>
__global__ void k_agg(const float* __restrict__ bias, float* __restrict__ outp) {
    int node = (blockIdx.x * blockDim.x + threadIdx.x) >> 5;
    if (node >= NN) return;
    int lane = threadIdx.x & 31;
    constexpr int VL = D / 32;

    const __half* H = (D == DH) ? g_h16 : g_h2_16;

    float acc[VL];
    #pragma unroll
    for (int k = 0; k < VL; k++) acc[k] = 0.f;

    int beg = g_rowptr[node], end = g_rowptr[node + 1];
    int j = beg;
    for (; j + 8 <= end; j += 8) {
        int2 p[8];
        #pragma unroll
        for (int i = 0; i < 8; i++) p[i] = __ldg(&g_epair[j + i]);
        if (D == DH) {
            uint2 u[8];
            #pragma unroll
            for (int i = 0; i < 8; i++)
                u[i] = __ldg((const uint2*)(H + (size_t)p[i].x * D) + lane);
            #pragma unroll
            for (int i = 0; i < 8; i++)
                acc128(acc, u[i], __int_as_float(p[i].y));
        } else {
            unsigned u[8];
            #pragma unroll
            for (int i = 0; i < 8; i++)
                u[i] = __ldg((const unsigned*)(H + (size_t)p[i].x * D) + lane);
            #pragma unroll
            for (int i = 0; i < 8; i++)
                acc64(acc, u[i], __int_as_float(p[i].y));
        }
    }
    for (; j < end; j++) {
        int2 p = __ldg(&g_epair[j]);
        float n = __int_as_float(p.y);
        if (D == DH) {
            uint2 u = __ldg((const uint2*)(H + (size_t)p.x * D) + lane);
            acc128(acc, u, n);
        } else {
            unsigned u = __ldg((const unsigned*)(H + (size_t)p.x * D) + lane);
            acc64(acc, u, n);
        }
    }

    float di = g_dinv[node], d2 = di * di;
    if (D == DH) {
        uint2 us = __ldg((const uint2*)(H + (size_t)node * D) + lane);
        float hv[4] = {0.f, 0.f, 0.f, 0.f};
        acc128(hv, us, d2);
        float4 bv = *(const float4*)(bias + lane * 4);
        float r0 = elu1(acc[0] + hv[0] + bv.x);
        float r1 = elu1(acc[1] + hv[1] + bv.y);
        float r2 = elu1(acc[2] + hv[2] + bv.z);
        float r3 = elu1(acc[3] + hv[3] + bv.w);
        __half2 o0 = __floats2half2_rn(r0, r1);
        __half2 o1 = __floats2half2_rn(r2, r3);
        *((uint2*)(g_agg16 + (size_t)node * D) + lane) =
            make_uint2(*reinterpret_cast<unsigned*>(&o0), *reinterpret_cast<unsigned*>(&o1));
    } else {
        unsigned us = __ldg((const unsigned*)(H + (size_t)node * D) + lane);
        float hv[2] = {0.f, 0.f};
        acc64(hv, us, d2);
        float2 bv = *(const float2*)(bias + lane * 2);
        float2 rr;
        rr.x = elu1(acc[0] + hv[0] + bv.x);
        rr.y = elu1(acc[1] + hv[1] + bv.y);
        *(float2*)(outp + (size_t)node * D + lane * 2) = rr;
    }
}

// ---------------------------------------------------------------
extern "C" void kernel_launch(void* const* d_in, const int* in_sizes, int n_in,
                              void* d_out, int out_size) {
    const float*    x  = (const float*)d_in[0];
    const unsigned* ei = (const unsigned*)d_in[1];
    const float*    W1 = (const float*)d_in[2];
    const float*    b1 = (const float*)d_in[3];
    const float*    W2 = (const float*)d_in[4];
    const float*    b2 = (const float*)d_in[5];
    float*          out = (float*)d_out;

    k_init  <<<(NN + 255) / 256, 256>>>(ei);            // 0
    k_count <<<(NE + 255) / 256, 256>>>(ei);            // 1
    k_wsplit<<<64, 256>>>(W1, W2);                      // 2
    k_mma<DH, 0><<<(NN + 127) / 128, 256>>>(x);         // 3 (profiled slot)
    k_p1    <<<NB, 1024>>>();                           // 4
    k_p2    <<<1, 128>>>();                             // 5
    k_p3    <<<NB, 1024>>>();                           // 6
    k_fill  <<<(NE + 255) / 256, 256>>>(ei);            // 7

    k_agg<DH><<<(NN * 32 + 255) / 256, 256>>>(b1, nullptr);   // 8
    k_mma<DO, 1><<<(NN + 127) / 128, 256>>>(nullptr);         // 9
    k_agg<DO><<<(NN * 32 + 255) / 256, 256>>>(b2, out);       // 10

    (void)in_sizes; (void)n_in; (void)out_size;
}